// round 7
// baseline (speedup 1.0000x reference)
#include <cuda_runtime.h>

#define BATCH 16
#define CHAN  3
#define HH 512
#define WW 512
#define TILE_ROWS 8
#define HALO 5
#define SROWS (TILE_ROWS + 2 * HALO)     // 18
#define NTHREADS 512
#define DELTA2 1e-6f

__global__ void zero_out_kernel(float* out, int n) {
    int i = blockIdx.x * blockDim.x + threadIdx.x;
    if (i < n) out[i] = 0.0f;
}

__global__ __launch_bounds__(NTHREADS, 3)
void photometric_kernel(const float* __restrict__ frame1,
                        const float* __restrict__ frame2,
                        const float* __restrict__ flow,
                        float* __restrict__ out) {
    __shared__ float s_tile[SROWS * WW];          // 36 KB: one channel's rows
    __shared__ float warp_sums[NTHREADS / 32];

    const int HW = HH * WW;
    const int tile = blockIdx.x;                  // 0..63
    const int c    = blockIdx.y;                  // 0..2
    const int b    = blockIdx.z;                  // 0..15
    const int ty0  = tile * TILE_ROWS;
    const int t_lo = max(0, ty0 - HALO);
    const int t_hi = min(HH - 1, ty0 + TILE_ROWS - 1 + HALO);
    const int nrows = t_hi - t_lo + 1;            // <= 18
    const int tid = threadIdx.x;

    const float* f2p = frame2 + ((size_t)b * CHAN + c) * HW;   // this channel's plane

    // ---- stage rows [t_lo, t_hi] of this channel (float4 coalesced) ----
    {
        const float4* src = (const float4*)(f2p + (size_t)t_lo * WW);
        float4* dst = (float4*)s_tile;
        const int n4 = nrows * (WW / 4);          // <= 2304
        for (int i = tid; i < n4; i += NTHREADS) dst[i] = src[i];
    }
    __syncthreads();

    const int x = tid;                            // full row per block
    const float scale = (float)(WW - 1) / (float)WW;   // W == H
    const float* f1p = frame1 + ((size_t)b * CHAN + c) * HW;
    const float* flx = flow + (size_t)(b * 2 + 0) * HW;
    const float* fly = flow + (size_t)(b * 2 + 1) * HW;
    const float xf = (float)x;

    float acc = 0.0f;

    #pragma unroll
    for (int r = 0; r < TILE_ROWS; r++) {
        const int y  = ty0 + r;
        const int hw = y * WW + x;

        const float fx = __ldg(flx + hw);
        const float fy = __ldg(fly + hw);

        float ix = (xf + fx) * scale;
        float iy = ((float)y + fy) * scale;
        ix = fminf(fmaxf(ix, 0.0f), (float)(WW - 1));
        iy = fminf(fmaxf(iy, 0.0f), (float)(HH - 1));

        // x0 = min(floor(ix), W-2), wx = ix - x0  (x1 = x0+1 always valid;
        // identical result at the ix == W-1 boundary since wx becomes 1.0)
        const int x0 = min((int)ix, WW - 2);
        const int y0 = min((int)iy, HH - 2);
        const float wx = ix - (float)x0;
        const float wy = iy - (float)y0;
        const int y1 = y0 + 1;

        const float f1v = __ldg(f1p + hw);

        float wv;
        if (y0 >= t_lo && y1 <= t_hi) {
            const int r0 = (y0 - t_lo) * WW + x0;
            const int r1 = r0 + WW;
            const float v00 = s_tile[r0];
            const float v01 = s_tile[r0 + 1];
            const float v10 = s_tile[r1];
            const float v11 = s_tile[r1 + 1];
            const float top = fmaf(v01 - v00, wx, v00);
            const float bot = fmaf(v11 - v10, wx, v10);
            wv = fmaf(bot - top, wy, top);
        } else {
            // |fy| > 5: ~a handful of pixels in the whole problem
            const int i00 = y0 * WW + x0;
            const float v00 = __ldg(f2p + i00);
            const float v01 = __ldg(f2p + i00 + 1);
            const float v10 = __ldg(f2p + i00 + WW);
            const float v11 = __ldg(f2p + i00 + WW + 1);
            const float top = fmaf(v01 - v00, wx, v00);
            const float bot = fmaf(v11 - v10, wx, v10);
            wv = fmaf(bot - top, wy, top);
        }

        const float d = f1v - wv;
        acc += __powf(fmaf(d, d, DELTA2), 0.45f);
    }

    // ---- block reduction ----
    #pragma unroll
    for (int off = 16; off > 0; off >>= 1)
        acc += __shfl_down_sync(0xFFFFFFFFu, acc, off);

    const int lane = tid & 31;
    const int wid  = tid >> 5;
    if (lane == 0) warp_sums[wid] = acc;
    __syncthreads();

    if (wid == 0) {
        float s = (lane < (NTHREADS / 32)) ? warp_sums[lane] : 0.0f;
        #pragma unroll
        for (int off = 8; off > 0; off >>= 1)
            s += __shfl_down_sync(0xFFFFFFFFu, s, off);
        if (lane == 0) atomicAdd(out, s);
    }
}

extern "C" void kernel_launch(void* const* d_in, const int* in_sizes, int n_in,
                              void* d_out, int out_size) {
    const float* frame1 = (const float*)d_in[0];
    const float* frame2 = (const float*)d_in[1];
    const float* flow   = (const float*)d_in[2];
    float* out = (float*)d_out;

    zero_out_kernel<<<(out_size + 255) / 256, 256>>>(out, out_size);

    dim3 grid(HH / TILE_ROWS, CHAN, BATCH);       // 64 x 3 x 16 = 3072 blocks
    photometric_kernel<<<grid, NTHREADS>>>(frame1, frame2, flow, out);
}

// round 9
// speedup vs baseline: 1.3886x; 1.3886x over previous
#include <cuda_runtime.h>

#define BATCH 16
#define CHAN  3
#define HH 512
#define WW 512
#define ROWS_PER_THREAD 4
#define NTHREADS 256
#define DELTA2 1e-6f

__global__ void zero_out_kernel(float* out, int n) {
    int i = blockIdx.x * blockDim.x + threadIdx.x;
    if (i < n) out[i] = 0.0f;
}

__global__ __launch_bounds__(NTHREADS, 4)   // 1024 thr/SM -> ~64-reg budget
void photometric_kernel(const float* __restrict__ frame1,
                        const float* __restrict__ frame2,
                        const float* __restrict__ flow,
                        float* __restrict__ out) {
    const int HW = HH * WW;
    const int x  = blockIdx.x * NTHREADS + threadIdx.x;   // lanes: 32 consecutive x
    const int y0 = blockIdx.y * ROWS_PER_THREAD;
    const int b  = blockIdx.z;

    const float* f1b = frame1 + (size_t)b * CHAN * HW;
    const float* f2b = frame2 + (size_t)b * CHAN * HW;
    const float* flx = flow + (size_t)(b * 2 + 0) * HW;
    const float* fly = flow + (size_t)(b * 2 + 1) * HW;
    const float scale = (float)(WW - 1) / (float)WW;      // W == H
    const float xf = (float)x;

    // ---- phase 1: flow loads + coords for all rows (independent chains) ----
    int idx00[ROWS_PER_THREAD];
    float wxa[ROWS_PER_THREAD], wya[ROWS_PER_THREAD];

    #pragma unroll
    for (int r = 0; r < ROWS_PER_THREAD; r++) {
        const int y  = y0 + r;
        const int hw = y * WW + x;
        const float fx = __ldg(flx + hw);
        const float fy = __ldg(fly + hw);

        float ix = (xf + fx) * scale;
        float iy = ((float)y + fy) * scale;
        ix = fminf(fmaxf(ix, 0.0f), (float)(WW - 1));
        iy = fminf(fmaxf(iy, 0.0f), (float)(HH - 1));

        // x0 = min(floor(ix), W-2); wx = ix - x0  (exact same result incl. boundary)
        const int x0 = min((int)ix, WW - 2);
        const int yi = min((int)iy, HH - 2);
        wxa[r] = ix - (float)x0;
        wya[r] = iy - (float)yi;
        idx00[r] = yi * WW + x0;
    }

    // ---- phase 2: gathers + math, rows unrolled (regs available for MLP) ----
    float acc = 0.0f;

    #pragma unroll
    for (int r = 0; r < ROWS_PER_THREAD; r++) {
        const int hw  = (y0 + r) * WW + x;
        const int i00 = idx00[r];
        const float wx = wxa[r];
        const float wy = wya[r];

        #pragma unroll
        for (int c = 0; c < CHAN; c++) {
            const float* p = f2b + (size_t)c * HW + i00;
            const float v00 = __ldg(p);
            const float v01 = __ldg(p + 1);
            const float v10 = __ldg(p + WW);
            const float v11 = __ldg(p + WW + 1);
            const float top = fmaf(v01 - v00, wx, v00);
            const float bot = fmaf(v11 - v10, wx, v10);
            const float wv  = fmaf(bot - top, wy, top);
            const float d = __ldg(f1b + c * HW + hw) - wv;
            acc += __powf(fmaf(d, d, DELTA2), 0.45f);
        }
    }

    // ---- block reduction ----
    #pragma unroll
    for (int off = 16; off > 0; off >>= 1)
        acc += __shfl_down_sync(0xFFFFFFFFu, acc, off);

    __shared__ float warp_sums[NTHREADS / 32];
    const int lane = threadIdx.x & 31;
    const int wid  = threadIdx.x >> 5;
    if (lane == 0) warp_sums[wid] = acc;
    __syncthreads();

    if (wid == 0) {
        float s = (lane < (NTHREADS / 32)) ? warp_sums[lane] : 0.0f;
        #pragma unroll
        for (int off = 4; off > 0; off >>= 1)
            s += __shfl_down_sync(0xFFFFFFFFu, s, off);
        if (lane == 0) atomicAdd(out, s);
    }
}

extern "C" void kernel_launch(void* const* d_in, const int* in_sizes, int n_in,
                              void* d_out, int out_size) {
    const float* frame1 = (const float*)d_in[0];
    const float* frame2 = (const float*)d_in[1];
    const float* flow   = (const float*)d_in[2];
    float* out = (float*)d_out;

    zero_out_kernel<<<(out_size + 255) / 256, 256>>>(out, out_size);

    dim3 grid(WW / NTHREADS, HH / ROWS_PER_THREAD, BATCH);  // 2 x 128 x 16
    photometric_kernel<<<grid, NTHREADS>>>(frame1, frame2, flow, out);
}